// round 2
// baseline (speedup 1.0000x reference)
#include <cuda_runtime.h>
#include <stdint.h>

// Problem constants (fixed by the dataset: N=8192, E=262144, C=256, H=256, MC=256)
#define NN 8192
#define EE 262144
#define CC 256

// Algebraic collapse:
// In fp32, ssum + 1e-16 == ssum, so segment_sum(att_sm) == 1.0 per (node,chan).
// assign[n,:] is therefore constant along channels -> S = softmax(assign) is the
// uniform 1/256 matrix (also for isolated nodes, where assign row == 0).
//   x_pooled[j,c]   = (1/256) * sum_n x[n,c]          (all 256 rows identical)
//   adj_pooled[i,j] = nnz_unique(row,col) / 65536     (scalar constant; adj set()
//                                                      dedupes repeated edges)

// Scratch: __device__ globals (no allocations allowed).
__device__ unsigned int g_bitmap[(NN * (long long)NN) / 32];  // 8 MB edge-uniqueness bitmap
__device__ int   g_cnt_part[1024];                            // per-block unique-edge counts
__device__ float g_partial[256 * CC];                         // per-block column partial sums
__device__ float g_colsum[CC];
__device__ int   g_count;

// ---------------------------------------------------------------------------
// Kernel 1: zero the bitmap (must happen every launch for graph replay).
// 2,097,152 uint words = 524,288 uint4. Grid 2048 x 256 exactly covers it.
__global__ void __launch_bounds__(256) k_zero_bitmap() {
    uint4* p = reinterpret_cast<uint4*>(g_bitmap);
    int i = blockIdx.x * blockDim.x + threadIdx.x;
    p[i] = make_uint4(0u, 0u, 0u, 0u);
}

// ---------------------------------------------------------------------------
// Kernel 2: mark edges in bitmap, count newly-set bits (unique edges).
// Grid 1024 x 256 = 262144 threads, one per edge.
// NOTE: edge_index is int32 on device (JAX default config downcasts jnp.int64).
__global__ void __launch_bounds__(256) k_edges(const int* __restrict__ ei) {
    int e = blockIdx.x * blockDim.x + threadIdx.x;
    int r = ei[e];        // edge_index[0, e]
    int c = ei[EE + e];   // edge_index[1, e]
    unsigned idx = (unsigned)r * (unsigned)NN + (unsigned)c;   // < 2^26
    unsigned m = 1u << (idx & 31u);
    unsigned old = atomicOr(&g_bitmap[idx >> 5], m);
    int nb = (old & m) ? 0 : 1;

    unsigned ball = __ballot_sync(0xffffffffu, nb);
    __shared__ int s[8];
    int lane = threadIdx.x & 31;
    int w = threadIdx.x >> 5;
    if (lane == 0) s[w] = __popc(ball);
    __syncthreads();
    if (threadIdx.x == 0) {
        int t = 0;
#pragma unroll
        for (int i = 0; i < 8; i++) t += s[i];
        g_cnt_part[blockIdx.x] = t;
    }
}

// ---------------------------------------------------------------------------
// Kernel 3: per-block column partial sums of x. 256 blocks x 256 threads.
// Block b handles rows [b*32, b*32+32). Coalesced: thread t reads column t.
__global__ void __launch_bounds__(256) k_colsum_part(const float* __restrict__ x) {
    int c = threadIdx.x;
    int r0 = blockIdx.x * 32;
    float s = 0.0f;
#pragma unroll
    for (int i = 0; i < 32; i++) s += x[(size_t)(r0 + i) * CC + c];
    g_partial[blockIdx.x * CC + c] = s;
}

// ---------------------------------------------------------------------------
// Kernel 4: deterministic final reductions (1 block, 256 threads).
__global__ void __launch_bounds__(256) k_reduce() {
    int t = threadIdx.x;

    // Column sums: fixed order over the 256 partials -> deterministic.
    float s = 0.0f;
    for (int b = 0; b < 256; b++) s += g_partial[b * CC + t];
    g_colsum[t] = s;

    // Unique-edge count: integer, fixed-order reduce of 1024 partials.
    int cs = g_cnt_part[t] + g_cnt_part[256 + t] + g_cnt_part[512 + t] + g_cnt_part[768 + t];
    __shared__ int sh[256];
    sh[t] = cs;
    __syncthreads();
    for (int o = 128; o > 0; o >>= 1) {
        if (t < o) sh[t] += sh[t + o];
        __syncthreads();
    }
    if (t == 0) g_count = sh[0];
}

// ---------------------------------------------------------------------------
// Kernel 5: write output. Layout: [x_pooled (256x256), adj_pooled (256x256)].
__global__ void __launch_bounds__(256) k_write(float* __restrict__ out, int out_size) {
    int i = blockIdx.x * blockDim.x + threadIdx.x;
    if (i >= out_size) return;
    if (i < 65536) {
        out[i] = g_colsum[i & 255] * (1.0f / 256.0f);
    } else {
        out[i] = (float)g_count * (1.0f / 65536.0f);
    }
}

// ---------------------------------------------------------------------------
extern "C" void kernel_launch(void* const* d_in, const int* in_sizes, int n_in,
                              void* d_out, int out_size) {
    const float* x  = (const float*)d_in[0];   // (N, C) f32
    const int*   ei = (const int*)d_in[1];     // (2, E) i32 (JAX downcasts int64)
    float* out = (float*)d_out;

    k_zero_bitmap<<<2048, 256>>>();
    k_edges<<<1024, 256>>>(ei);
    k_colsum_part<<<256, 256>>>(x);
    k_reduce<<<1, 256>>>();
    int nblk = (out_size + 255) / 256;
    k_write<<<nblk, 256>>>(out, out_size);
}